// round 11
// baseline (speedup 1.0000x reference)
#include <cuda_runtime.h>
#include <cuda_fp16.h>
#include <cstdint>

#define N_USERS 200000
#define N_ITEMS 100000
#define N_TOTAL 300000
#define DIM     64
#define N_EDGES 4800000
#define BATCH   16384
#define PAD     64          // padded slots per row; P(deg>64) ~ e^-45 for Poisson(16)

#define NWARPCH (N_TOTAL / 4)   // 75000 sorted 4-row chunks (one per warp)
#define WSTRIDE 593             // coprime with 75000 -> uniform wave sampling

#define SCAT_BLOCKS ((N_EDGES / 4 + 255) / 256)          // 4688
#define CONV_BLOCKS ((N_TOTAL * DIM / 4 + 255) / 256)    // 18750

// ---------------------------------------------------------------------------
// Device-global scratch (no allocation allowed).
// ---------------------------------------------------------------------------
__device__ __half g_B16[N_TOTAL * DIM];              // fp16 copy of base embeddings
__device__ __half g_E1 [N_TOTAL * DIM];              // layer-1 output (fp16)
__device__ __half g_E2 [N_TOTAL * DIM];              // layer-2 output (fp16)
__device__ int    g_cnt [N_TOTAL];                   // per-row degree counters
__device__ int2   g_edges[(size_t)N_TOTAL * PAD];    // padded CSR {src, val bits}
__device__ int    g_bins  [PAD + 1];                 // degree histogram
__device__ int    g_bincur[PAD + 1];                 // per-bin running cursors
__device__ int    g_order [N_TOTAL];                 // rows sorted by degree

__device__ __forceinline__ unsigned h2u(__half2 h)
{
    return *reinterpret_cast<unsigned*>(&h);
}

// ---------------------------------------------------------------------------
// Fused: base->fp16 convert AND one-pass padded-CSR scatter (independent
// work split by block range; cnt[] pre-zeroed via cudaMemsetAsync).
// ---------------------------------------------------------------------------
__global__ void build_kernel(const float*  __restrict__ ue,
                             const float*  __restrict__ ie,
                             __half*       __restrict__ b16,
                             const int4*   __restrict__ es4,
                             const int4*   __restrict__ ed4,
                             const float4* __restrict__ ev4,
                             int* cnt, int2* edges)
{
    if (blockIdx.x < SCAT_BLOCKS) {
        // --- scatter part: 4 edges per thread ---
        int i = blockIdx.x * blockDim.x + threadIdx.x;
        if (i >= N_EDGES / 4) return;
        int4   s = __ldcs(&es4[i]);
        int4   d = __ldcs(&ed4[i]);
        float4 v = __ldcs(&ev4[i]);
        int p0 = atomicAdd(&cnt[d.x], 1);
        int p1 = atomicAdd(&cnt[d.y], 1);
        int p2 = atomicAdd(&cnt[d.z], 1);
        int p3 = atomicAdd(&cnt[d.w], 1);
        if (p0 < PAD) edges[(size_t)d.x * PAD + p0] = make_int2(s.x, __float_as_int(v.x));
        if (p1 < PAD) edges[(size_t)d.y * PAD + p1] = make_int2(s.y, __float_as_int(v.y));
        if (p2 < PAD) edges[(size_t)d.z * PAD + p2] = make_int2(s.z, __float_as_int(v.z));
        if (p3 < PAD) edges[(size_t)d.w * PAD + p3] = make_int2(s.w, __float_as_int(v.w));
    } else {
        // --- convert part ---
        const int total4 = N_TOTAL * DIM / 4;
        const int user4  = N_USERS * DIM / 4;
        int i = (blockIdx.x - SCAT_BLOCKS) * blockDim.x + threadIdx.x;
        if (i >= total4) return;
        float4 v = (i < user4) ? __ldg(reinterpret_cast<const float4*>(ue) + i)
                               : __ldg(reinterpret_cast<const float4*>(ie) + (i - user4));
        uint2 o;
        o.x = h2u(__float22half2_rn(make_float2(v.x, v.y)));
        o.y = h2u(__float22half2_rn(make_float2(v.z, v.w)));
        reinterpret_cast<uint2*>(b16)[i] = o;
    }
}

// ---------------------------------------------------------------------------
// degree histogram (shared-memory aggregated)
// ---------------------------------------------------------------------------
__global__ void deghist_kernel(const int* __restrict__ cnt, int* bins)
{
    __shared__ int h[PAD + 1];
    if (threadIdx.x <= PAD) h[threadIdx.x] = 0;
    __syncthreads();
    int i = blockIdx.x * blockDim.x + threadIdx.x;
    if (i < N_TOTAL) {
        int d = cnt[i]; d = (d > PAD) ? PAD : d;
        atomicAdd(&h[d], 1);
    }
    __syncthreads();
    if (threadIdx.x <= PAD && h[threadIdx.x] > 0)
        atomicAdd(&bins[threadIdx.x], h[threadIdx.x]);
}

// place rows into degree-sorted order; each block computes the 65-bin
// exclusive scan locally (global bins[] is final).
__global__ void place_kernel(const int* __restrict__ cnt,
                             const int* __restrict__ bins,
                             int* bincur, int* order)
{
    __shared__ int h[PAD + 1];
    __shared__ int base[PAD + 1];
    __shared__ int scan[PAD + 1];
    int tid = threadIdx.x;
    if (tid <= PAD) h[tid] = 0;
    if (tid == 0) {
        int run = 0;
        #pragma unroll
        for (int b = 0; b <= PAD; ++b) { scan[b] = run; run += __ldg(&bins[b]); }
    }
    __syncthreads();
    int i = blockIdx.x * blockDim.x + tid;
    int deg = 0, lpos = 0;
    if (i < N_TOTAL) {
        deg = cnt[i]; deg = (deg > PAD) ? PAD : deg;
        lpos = atomicAdd(&h[deg], 1);
    }
    __syncthreads();
    if (tid <= PAD)
        base[tid] = scan[tid] + ((h[tid] > 0) ? atomicAdd(&bincur[tid], h[tid]) : 0);
    __syncthreads();
    if (i < N_TOTAL) order[base[deg] + lpos] = i;
}

// ---------------------------------------------------------------------------
// fp16 row-wise SpMM over degree-sorted rows, coprime warp->chunk remap,
// software-pipelined edge loads. Edge reads use __ldcs (evict-first) so the
// 153 MB edge stream never evicts the L2-resident gather tables.
// 8 lanes per dst row; each lane owns one 16-byte chunk. fp32 accumulation.
// ---------------------------------------------------------------------------
__device__ __forceinline__ void fma8(float acc[8], float v, uint4 raw)
{
    float2 f0 = __half22float2(*reinterpret_cast<__half2*>(&raw.x));
    float2 f1 = __half22float2(*reinterpret_cast<__half2*>(&raw.y));
    float2 f2 = __half22float2(*reinterpret_cast<__half2*>(&raw.z));
    float2 f3 = __half22float2(*reinterpret_cast<__half2*>(&raw.w));
    acc[0] += v * f0.x; acc[1] += v * f0.y;
    acc[2] += v * f1.x; acc[3] += v * f1.y;
    acc[4] += v * f2.x; acc[5] += v * f2.y;
    acc[6] += v * f3.x; acc[7] += v * f3.y;
}

__global__ void spmm_h_kernel(const __half* __restrict__ src,
                              __half*       __restrict__ dst,
                              const int*    __restrict__ cnt,
                              const int2*   __restrict__ edges,
                              const int*    __restrict__ order)
{
    int gid   = blockIdx.x * blockDim.x + threadIdx.x;
    int warp  = gid >> 5;                      // global warp id, [0, NWARPCH)
    if (warp >= NWARPCH) return;
    int sub   = (threadIdx.x >> 3) & 3;        // 4 subwarps of 8 lanes
    int lane  = threadIdx.x & 7;

    // coprime remap: warp -> sorted 4-row chunk (uniform degree per wave)
    long long c = ((long long)warp * WSTRIDE) % NWARPCH;
    int ridx = (int)c * 4 + sub;
    int row  = __ldg(&order[ridx]);

    int deg = __ldg(&cnt[row]);
    deg = (deg > PAD) ? PAD : deg;
    const int2* erow = edges + (size_t)row * PAD;

    float acc[8] = {0.f, 0.f, 0.f, 0.f, 0.f, 0.f, 0.f, 0.f};

    int j = 0;
    if (deg >= 4) {
        int4 q0 = __ldcs(reinterpret_cast<const int4*>(erow));
        int4 q1 = __ldcs(reinterpret_cast<const int4*>(erow + 2));
        for (; j + 7 < deg; j += 4) {
            int4 n0 = __ldcs(reinterpret_cast<const int4*>(erow + j + 4));
            int4 n1 = __ldcs(reinterpret_cast<const int4*>(erow + j + 6));
            uint4 r0 = __ldg(reinterpret_cast<const uint4*>(src + (size_t)q0.x * DIM) + lane);
            uint4 r1 = __ldg(reinterpret_cast<const uint4*>(src + (size_t)q0.z * DIM) + lane);
            uint4 r2 = __ldg(reinterpret_cast<const uint4*>(src + (size_t)q1.x * DIM) + lane);
            uint4 r3 = __ldg(reinterpret_cast<const uint4*>(src + (size_t)q1.z * DIM) + lane);
            fma8(acc, __int_as_float(q0.y), r0);
            fma8(acc, __int_as_float(q0.w), r1);
            fma8(acc, __int_as_float(q1.y), r2);
            fma8(acc, __int_as_float(q1.w), r3);
            q0 = n0; q1 = n1;
        }
        // drain the held quad (edges j..j+3, guaranteed valid)
        {
            uint4 r0 = __ldg(reinterpret_cast<const uint4*>(src + (size_t)q0.x * DIM) + lane);
            uint4 r1 = __ldg(reinterpret_cast<const uint4*>(src + (size_t)q0.z * DIM) + lane);
            uint4 r2 = __ldg(reinterpret_cast<const uint4*>(src + (size_t)q1.x * DIM) + lane);
            uint4 r3 = __ldg(reinterpret_cast<const uint4*>(src + (size_t)q1.z * DIM) + lane);
            fma8(acc, __int_as_float(q0.y), r0);
            fma8(acc, __int_as_float(q0.w), r1);
            fma8(acc, __int_as_float(q1.y), r2);
            fma8(acc, __int_as_float(q1.w), r3);
            j += 4;
        }
    }
    if (j + 1 < deg) {
        int4 q0 = __ldcs(reinterpret_cast<const int4*>(erow + j));
        uint4 r0 = __ldg(reinterpret_cast<const uint4*>(src + (size_t)q0.x * DIM) + lane);
        uint4 r1 = __ldg(reinterpret_cast<const uint4*>(src + (size_t)q0.z * DIM) + lane);
        fma8(acc, __int_as_float(q0.y), r0);
        fma8(acc, __int_as_float(q0.w), r1);
        j += 2;
    }
    if (j < deg) {
        int2 p0 = __ldcs(&erow[j]);
        uint4 r0 = __ldg(reinterpret_cast<const uint4*>(src + (size_t)p0.x * DIM) + lane);
        fma8(acc, __int_as_float(p0.y), r0);
    }

    uint4 o;
    o.x = h2u(__float22half2_rn(make_float2(acc[0], acc[1])));
    o.y = h2u(__float22half2_rn(make_float2(acc[2], acc[3])));
    o.z = h2u(__float22half2_rn(make_float2(acc[4], acc[5])));
    o.w = h2u(__float22half2_rn(make_float2(acc[6], acc[7])));
    reinterpret_cast<uint4*>(dst + (size_t)row * DIM)[lane] = o;
}

// ---------------------------------------------------------------------------
// Fused layer-3 + final gather. One warp per batch entry; each lane owns a
// half2 column pair. Pipelined edge loop, __ldcs edge reads.
// Output layout: [users_emb B*64][items_emb B*64][scores B]
// ---------------------------------------------------------------------------
__device__ __forceinline__ float2 final_row(int row,
                                            const float*  __restrict__ base_row_ptr,
                                            const __half* __restrict__ e1,
                                            const __half* __restrict__ e2,
                                            const int*    __restrict__ cnt,
                                            const int2*   __restrict__ edges,
                                            int lane)
{
    float ax = 0.f, ay = 0.f;
    int deg = __ldg(&cnt[row]);
    deg = (deg > PAD) ? PAD : deg;
    const int2* erow = edges + (size_t)row * PAD;

    int j = 0;
    if (deg >= 4) {
        int4 q0 = __ldcs(reinterpret_cast<const int4*>(erow));
        int4 q1 = __ldcs(reinterpret_cast<const int4*>(erow + 2));
        for (; j + 7 < deg; j += 4) {
            int4 n0 = __ldcs(reinterpret_cast<const int4*>(erow + j + 4));
            int4 n1 = __ldcs(reinterpret_cast<const int4*>(erow + j + 6));
            float2 f0 = __half22float2(
                __ldg(reinterpret_cast<const __half2*>(e2 + (size_t)q0.x * DIM) + lane));
            float2 f1 = __half22float2(
                __ldg(reinterpret_cast<const __half2*>(e2 + (size_t)q0.z * DIM) + lane));
            float2 f2 = __half22float2(
                __ldg(reinterpret_cast<const __half2*>(e2 + (size_t)q1.x * DIM) + lane));
            float2 f3 = __half22float2(
                __ldg(reinterpret_cast<const __half2*>(e2 + (size_t)q1.z * DIM) + lane));
            ax += __int_as_float(q0.y) * f0.x + __int_as_float(q0.w) * f1.x
                + __int_as_float(q1.y) * f2.x + __int_as_float(q1.w) * f3.x;
            ay += __int_as_float(q0.y) * f0.y + __int_as_float(q0.w) * f1.y
                + __int_as_float(q1.y) * f2.y + __int_as_float(q1.w) * f3.y;
            q0 = n0; q1 = n1;
        }
        {
            float2 f0 = __half22float2(
                __ldg(reinterpret_cast<const __half2*>(e2 + (size_t)q0.x * DIM) + lane));
            float2 f1 = __half22float2(
                __ldg(reinterpret_cast<const __half2*>(e2 + (size_t)q0.z * DIM) + lane));
            float2 f2 = __half22float2(
                __ldg(reinterpret_cast<const __half2*>(e2 + (size_t)q1.x * DIM) + lane));
            float2 f3 = __half22float2(
                __ldg(reinterpret_cast<const __half2*>(e2 + (size_t)q1.z * DIM) + lane));
            ax += __int_as_float(q0.y) * f0.x + __int_as_float(q0.w) * f1.x
                + __int_as_float(q1.y) * f2.x + __int_as_float(q1.w) * f3.x;
            ay += __int_as_float(q0.y) * f0.y + __int_as_float(q0.w) * f1.y
                + __int_as_float(q1.y) * f2.y + __int_as_float(q1.w) * f3.y;
            j += 4;
        }
    }
    for (; j < deg; ++j) {
        int2 p = __ldcs(&erow[j]);
        float v = __int_as_float(p.y);
        float2 f = __half22float2(
            __ldg(reinterpret_cast<const __half2*>(e2 + (size_t)p.x * DIM) + lane));
        ax += v * f.x;
        ay += v * f.y;
    }
    float2 b  = reinterpret_cast<const float2*>(base_row_ptr)[lane];
    float2 f1 = __half22float2(
        __ldg(reinterpret_cast<const __half2*>(e1 + (size_t)row * DIM) + lane));
    float2 f2 = __half22float2(
        __ldg(reinterpret_cast<const __half2*>(e2 + (size_t)row * DIM) + lane));
    return make_float2((b.x + f1.x + f2.x + ax) * 0.25f,
                       (b.y + f1.y + f2.y + ay) * 0.25f);
}

__global__ void gather3_kernel(const float*  __restrict__ ue,
                               const float*  __restrict__ ie,
                               const __half* __restrict__ e1,
                               const __half* __restrict__ e2,
                               const int*    __restrict__ cnt,
                               const int2*   __restrict__ edges,
                               const int*    __restrict__ users,
                               const int*    __restrict__ items,
                               float*        __restrict__ out)
{
    int w    = (blockIdx.x * blockDim.x + threadIdx.x) >> 5;
    int lane = threadIdx.x & 31;
    if (w >= BATCH) return;

    int u = users[w];
    int t = items[w] + N_USERS;

    float2 uemb = final_row(u, ue + (size_t)u * DIM, e1, e2, cnt, edges, lane);
    float2 iemb = final_row(t, ie + (size_t)(t - N_USERS) * DIM, e1, e2, cnt, edges, lane);

    reinterpret_cast<float2*>(out + (size_t)w * DIM)[lane] = uemb;
    reinterpret_cast<float2*>(out + (size_t)BATCH * DIM + (size_t)w * DIM)[lane] = iemb;

    float dot = uemb.x * iemb.x + uemb.y * iemb.y;
    #pragma unroll
    for (int off = 16; off > 0; off >>= 1)
        dot += __shfl_down_sync(0xFFFFFFFFu, dot, off);
    if (lane == 0)
        out[(size_t)2 * BATCH * DIM + w] = dot;
}

// ---------------------------------------------------------------------------
// Launch. Inputs per metadata order:
//  0 user_embed f32  1 item_embed f32  2 edge_src i32  3 edge_dst i32
//  4 edge_val f32    5 users i32       6 items i32
// ---------------------------------------------------------------------------
extern "C" void kernel_launch(void* const* d_in, const int* in_sizes, int n_in,
                              void* d_out, int out_size)
{
    const float* ue = (const float*)d_in[0];
    const float* ie = (const float*)d_in[1];
    const int*   es = (const int*)  d_in[2];
    const int*   ed = (const int*)  d_in[3];
    const float* ev = (const float*)d_in[4];
    const int*   us = (const int*)  d_in[5];
    const int*   it = (const int*)  d_in[6];
    float* out = (float*)d_out;

    __half *b16, *e1, *e2;
    int *cnt, *bins, *bincur, *order;
    int2 *edges;
    cudaGetSymbolAddress((void**)&b16,    g_B16);
    cudaGetSymbolAddress((void**)&e1,     g_E1);
    cudaGetSymbolAddress((void**)&e2,     g_E2);
    cudaGetSymbolAddress((void**)&cnt,    g_cnt);
    cudaGetSymbolAddress((void**)&edges,  g_edges);
    cudaGetSymbolAddress((void**)&bins,   g_bins);
    cudaGetSymbolAddress((void**)&bincur, g_bincur);
    cudaGetSymbolAddress((void**)&order,  g_order);

    const int spmm_blocks = (N_TOTAL * 8 + 255) / 256;
    const int sort_blocks = (N_TOTAL + 1023) / 1024;

    // zero counters (async memset is graph-capturable, not an allocation)
    cudaMemsetAsync(cnt,    0, N_TOTAL * sizeof(int));
    cudaMemsetAsync(bins,   0, (PAD + 1) * sizeof(int));
    cudaMemsetAsync(bincur, 0, (PAD + 1) * sizeof(int));

    // --- fused convert + padded-CSR scatter ---
    build_kernel<<<SCAT_BLOCKS + CONV_BLOCKS, 256>>>(
        ue, ie, b16, (const int4*)es, (const int4*)ed, (const float4*)ev,
        cnt, edges);

    // --- degree sort of rows (counting sort, 65 bins; scan fused into place) ---
    deghist_kernel<<<sort_blocks, 1024>>>(cnt, bins);
    place_kernel  <<<sort_blocks, 1024>>>(cnt, bins, bincur, order);

    // --- 2 fp16 SpMM layers over degree-sorted rows ---
    spmm_h_kernel<<<spmm_blocks, 256>>>(b16, e1, cnt, edges, order);
    spmm_h_kernel<<<spmm_blocks, 256>>>(e1,  e2, cnt, edges, order);

    // --- fused layer-3 + gather + dot ---
    gather3_kernel<<<(BATCH * 32 + 255) / 256, 256>>>(ue, ie, e1, e2, cnt, edges,
                                                      us, it, out);
}

// round 12
// speedup vs baseline: 1.0108x; 1.0108x over previous
#include <cuda_runtime.h>
#include <cuda_fp16.h>
#include <cstdint>

#define N_USERS 200000
#define N_ITEMS 100000
#define N_TOTAL 300000
#define DIM     64
#define N_EDGES 4800000
#define BATCH   16384
#define PAD     64          // padded slots per row; P(deg>64) ~ e^-45 for Poisson(16)

#define NWARPCH (N_TOTAL / 4)   // 75000 sorted 4-row chunks (one per warp)
#define WSTRIDE 593             // coprime with 75000 -> uniform wave sampling

// ---------------------------------------------------------------------------
// Device-global scratch (no allocation allowed).
// ---------------------------------------------------------------------------
__device__ __half g_B16[N_TOTAL * DIM];              // fp16 copy of base embeddings
__device__ __half g_E1 [N_TOTAL * DIM];              // layer-1 output (fp16)
__device__ __half g_E2 [N_TOTAL * DIM];              // layer-2 output (fp16)
__device__ int    g_cnt [N_TOTAL];                   // per-row degree counters
__device__ int2   g_edges[(size_t)N_TOTAL * PAD];    // padded CSR {src, val bits}
__device__ int    g_bins  [PAD + 1];                 // degree histogram
__device__ int    g_bincur[PAD + 1];                 // per-bin running cursors
__device__ int    g_order [N_TOTAL];                 // rows sorted by degree

__device__ __forceinline__ unsigned h2u(__half2 h)
{
    return *reinterpret_cast<unsigned*>(&h);
}

// ---------------------------------------------------------------------------
// base -> fp16 table; also zero cnt[], bins[], bincur[]
// ---------------------------------------------------------------------------
__global__ void convert_base_kernel(const float* __restrict__ ue,
                                    const float* __restrict__ ie,
                                    __half* __restrict__ b16,
                                    int* __restrict__ cnt,
                                    int* __restrict__ bins,
                                    int* __restrict__ bincur)
{
    const int total4 = N_TOTAL * DIM / 4;
    const int user4  = N_USERS * DIM / 4;
    int i = blockIdx.x * blockDim.x + threadIdx.x;
    if (i < N_TOTAL) cnt[i] = 0;
    if (i <= PAD)  { bins[i] = 0; bincur[i] = 0; }
    if (i >= total4) return;
    float4 v = (i < user4) ? __ldg(reinterpret_cast<const float4*>(ue) + i)
                           : __ldg(reinterpret_cast<const float4*>(ie) + (i - user4));
    uint2 o;
    o.x = h2u(__float22half2_rn(make_float2(v.x, v.y)));
    o.y = h2u(__float22half2_rn(make_float2(v.z, v.w)));
    reinterpret_cast<uint2*>(b16)[i] = o;
}

// ---------------------------------------------------------------------------
// one-pass padded-CSR build (streaming reads evict-first)
// ---------------------------------------------------------------------------
__global__ void pad_scatter_kernel(const int4*   __restrict__ es4,
                                   const int4*   __restrict__ ed4,
                                   const float4* __restrict__ ev4,
                                   int* cnt, int2* edges)
{
    int i = blockIdx.x * blockDim.x + threadIdx.x;
    if (i >= N_EDGES / 4) return;
    int4   s = __ldcs(&es4[i]);
    int4   d = __ldcs(&ed4[i]);
    float4 v = __ldcs(&ev4[i]);
    int p0 = atomicAdd(&cnt[d.x], 1);
    int p1 = atomicAdd(&cnt[d.y], 1);
    int p2 = atomicAdd(&cnt[d.z], 1);
    int p3 = atomicAdd(&cnt[d.w], 1);
    if (p0 < PAD) edges[(size_t)d.x * PAD + p0] = make_int2(s.x, __float_as_int(v.x));
    if (p1 < PAD) edges[(size_t)d.y * PAD + p1] = make_int2(s.y, __float_as_int(v.y));
    if (p2 < PAD) edges[(size_t)d.z * PAD + p2] = make_int2(s.z, __float_as_int(v.z));
    if (p3 < PAD) edges[(size_t)d.w * PAD + p3] = make_int2(s.w, __float_as_int(v.w));
}

// ---------------------------------------------------------------------------
// degree histogram (shared-memory aggregated)
// ---------------------------------------------------------------------------
__global__ void deghist_kernel(const int* __restrict__ cnt, int* bins)
{
    __shared__ int h[PAD + 1];
    if (threadIdx.x <= PAD) h[threadIdx.x] = 0;
    __syncthreads();
    int i = blockIdx.x * blockDim.x + threadIdx.x;
    if (i < N_TOTAL) {
        int d = cnt[i]; d = (d > PAD) ? PAD : d;
        atomicAdd(&h[d], 1);
    }
    __syncthreads();
    if (threadIdx.x <= PAD && h[threadIdx.x] > 0)
        atomicAdd(&bins[threadIdx.x], h[threadIdx.x]);
}

// place rows into degree-sorted order; each block computes the 65-bin
// exclusive scan locally (global bins[] is final).
__global__ void place_kernel(const int* __restrict__ cnt,
                             const int* __restrict__ bins,
                             int* bincur, int* order)
{
    __shared__ int h[PAD + 1];
    __shared__ int base[PAD + 1];
    __shared__ int scan[PAD + 1];
    int tid = threadIdx.x;
    if (tid <= PAD) h[tid] = 0;
    if (tid == 0) {
        int run = 0;
        #pragma unroll
        for (int b = 0; b <= PAD; ++b) { scan[b] = run; run += __ldg(&bins[b]); }
    }
    __syncthreads();
    int i = blockIdx.x * blockDim.x + tid;
    int deg = 0, lpos = 0;
    if (i < N_TOTAL) {
        deg = cnt[i]; deg = (deg > PAD) ? PAD : deg;
        lpos = atomicAdd(&h[deg], 1);
    }
    __syncthreads();
    if (tid <= PAD)
        base[tid] = scan[tid] + ((h[tid] > 0) ? atomicAdd(&bincur[tid], h[tid]) : 0);
    __syncthreads();
    if (i < N_TOTAL) order[base[deg] + lpos] = i;
}

// ---------------------------------------------------------------------------
// fp16 row-wise SpMM over degree-sorted rows, coprime warp->chunk remap,
// software-pipelined edge loads. Edge reads use __ldcs (evict-first) so the
// edge stream never evicts the L2-resident gather tables.
// 8 lanes per dst row; each lane owns one 16-byte chunk. fp32 accumulation.
// ---------------------------------------------------------------------------
__device__ __forceinline__ void fma8(float acc[8], float v, uint4 raw)
{
    float2 f0 = __half22float2(*reinterpret_cast<__half2*>(&raw.x));
    float2 f1 = __half22float2(*reinterpret_cast<__half2*>(&raw.y));
    float2 f2 = __half22float2(*reinterpret_cast<__half2*>(&raw.z));
    float2 f3 = __half22float2(*reinterpret_cast<__half2*>(&raw.w));
    acc[0] += v * f0.x; acc[1] += v * f0.y;
    acc[2] += v * f1.x; acc[3] += v * f1.y;
    acc[4] += v * f2.x; acc[5] += v * f2.y;
    acc[6] += v * f3.x; acc[7] += v * f3.y;
}

__global__ void spmm_h_kernel(const __half* __restrict__ src,
                              __half*       __restrict__ dst,
                              const int*    __restrict__ cnt,
                              const int2*   __restrict__ edges,
                              const int*    __restrict__ order)
{
    int gid   = blockIdx.x * blockDim.x + threadIdx.x;
    int warp  = gid >> 5;                      // global warp id, [0, NWARPCH)
    if (warp >= NWARPCH) return;
    int sub   = (threadIdx.x >> 3) & 3;        // 4 subwarps of 8 lanes
    int lane  = threadIdx.x & 7;

    // coprime remap: warp -> sorted 4-row chunk (uniform degree per wave)
    long long c = ((long long)warp * WSTRIDE) % NWARPCH;
    int ridx = (int)c * 4 + sub;
    int row  = __ldg(&order[ridx]);

    int deg = __ldg(&cnt[row]);
    deg = (deg > PAD) ? PAD : deg;
    const int2* erow = edges + (size_t)row * PAD;

    float acc[8] = {0.f, 0.f, 0.f, 0.f, 0.f, 0.f, 0.f, 0.f};

    int j = 0;
    if (deg >= 4) {
        int4 q0 = __ldcs(reinterpret_cast<const int4*>(erow));
        int4 q1 = __ldcs(reinterpret_cast<const int4*>(erow + 2));
        for (; j + 7 < deg; j += 4) {
            int4 n0 = __ldcs(reinterpret_cast<const int4*>(erow + j + 4));
            int4 n1 = __ldcs(reinterpret_cast<const int4*>(erow + j + 6));
            uint4 r0 = __ldg(reinterpret_cast<const uint4*>(src + (size_t)q0.x * DIM) + lane);
            uint4 r1 = __ldg(reinterpret_cast<const uint4*>(src + (size_t)q0.z * DIM) + lane);
            uint4 r2 = __ldg(reinterpret_cast<const uint4*>(src + (size_t)q1.x * DIM) + lane);
            uint4 r3 = __ldg(reinterpret_cast<const uint4*>(src + (size_t)q1.z * DIM) + lane);
            fma8(acc, __int_as_float(q0.y), r0);
            fma8(acc, __int_as_float(q0.w), r1);
            fma8(acc, __int_as_float(q1.y), r2);
            fma8(acc, __int_as_float(q1.w), r3);
            q0 = n0; q1 = n1;
        }
        // drain the held quad (edges j..j+3, guaranteed valid)
        {
            uint4 r0 = __ldg(reinterpret_cast<const uint4*>(src + (size_t)q0.x * DIM) + lane);
            uint4 r1 = __ldg(reinterpret_cast<const uint4*>(src + (size_t)q0.z * DIM) + lane);
            uint4 r2 = __ldg(reinterpret_cast<const uint4*>(src + (size_t)q1.x * DIM) + lane);
            uint4 r3 = __ldg(reinterpret_cast<const uint4*>(src + (size_t)q1.z * DIM) + lane);
            fma8(acc, __int_as_float(q0.y), r0);
            fma8(acc, __int_as_float(q0.w), r1);
            fma8(acc, __int_as_float(q1.y), r2);
            fma8(acc, __int_as_float(q1.w), r3);
            j += 4;
        }
    }
    if (j + 1 < deg) {
        int4 q0 = __ldcs(reinterpret_cast<const int4*>(erow + j));
        uint4 r0 = __ldg(reinterpret_cast<const uint4*>(src + (size_t)q0.x * DIM) + lane);
        uint4 r1 = __ldg(reinterpret_cast<const uint4*>(src + (size_t)q0.z * DIM) + lane);
        fma8(acc, __int_as_float(q0.y), r0);
        fma8(acc, __int_as_float(q0.w), r1);
        j += 2;
    }
    if (j < deg) {
        int2 p0 = __ldcs(&erow[j]);
        uint4 r0 = __ldg(reinterpret_cast<const uint4*>(src + (size_t)p0.x * DIM) + lane);
        fma8(acc, __int_as_float(p0.y), r0);
    }

    uint4 o;
    o.x = h2u(__float22half2_rn(make_float2(acc[0], acc[1])));
    o.y = h2u(__float22half2_rn(make_float2(acc[2], acc[3])));
    o.z = h2u(__float22half2_rn(make_float2(acc[4], acc[5])));
    o.w = h2u(__float22half2_rn(make_float2(acc[6], acc[7])));
    reinterpret_cast<uint4*>(dst + (size_t)row * DIM)[lane] = o;
}

// ---------------------------------------------------------------------------
// Fused layer-3 + final gather. One warp per batch entry; each lane owns a
// half2 column pair. Pipelined edge loop, __ldcs edge reads.
// Output layout: [users_emb B*64][items_emb B*64][scores B]
// ---------------------------------------------------------------------------
__device__ __forceinline__ float2 final_row(int row,
                                            const float*  __restrict__ base_row_ptr,
                                            const __half* __restrict__ e1,
                                            const __half* __restrict__ e2,
                                            const int*    __restrict__ cnt,
                                            const int2*   __restrict__ edges,
                                            int lane)
{
    float ax = 0.f, ay = 0.f;
    int deg = __ldg(&cnt[row]);
    deg = (deg > PAD) ? PAD : deg;
    const int2* erow = edges + (size_t)row * PAD;

    int j = 0;
    if (deg >= 4) {
        int4 q0 = __ldcs(reinterpret_cast<const int4*>(erow));
        int4 q1 = __ldcs(reinterpret_cast<const int4*>(erow + 2));
        for (; j + 7 < deg; j += 4) {
            int4 n0 = __ldcs(reinterpret_cast<const int4*>(erow + j + 4));
            int4 n1 = __ldcs(reinterpret_cast<const int4*>(erow + j + 6));
            float2 f0 = __half22float2(
                __ldg(reinterpret_cast<const __half2*>(e2 + (size_t)q0.x * DIM) + lane));
            float2 f1 = __half22float2(
                __ldg(reinterpret_cast<const __half2*>(e2 + (size_t)q0.z * DIM) + lane));
            float2 f2 = __half22float2(
                __ldg(reinterpret_cast<const __half2*>(e2 + (size_t)q1.x * DIM) + lane));
            float2 f3 = __half22float2(
                __ldg(reinterpret_cast<const __half2*>(e2 + (size_t)q1.z * DIM) + lane));
            ax += __int_as_float(q0.y) * f0.x + __int_as_float(q0.w) * f1.x
                + __int_as_float(q1.y) * f2.x + __int_as_float(q1.w) * f3.x;
            ay += __int_as_float(q0.y) * f0.y + __int_as_float(q0.w) * f1.y
                + __int_as_float(q1.y) * f2.y + __int_as_float(q1.w) * f3.y;
            q0 = n0; q1 = n1;
        }
        {
            float2 f0 = __half22float2(
                __ldg(reinterpret_cast<const __half2*>(e2 + (size_t)q0.x * DIM) + lane));
            float2 f1 = __half22float2(
                __ldg(reinterpret_cast<const __half2*>(e2 + (size_t)q0.z * DIM) + lane));
            float2 f2 = __half22float2(
                __ldg(reinterpret_cast<const __half2*>(e2 + (size_t)q1.x * DIM) + lane));
            float2 f3 = __half22float2(
                __ldg(reinterpret_cast<const __half2*>(e2 + (size_t)q1.z * DIM) + lane));
            ax += __int_as_float(q0.y) * f0.x + __int_as_float(q0.w) * f1.x
                + __int_as_float(q1.y) * f2.x + __int_as_float(q1.w) * f3.x;
            ay += __int_as_float(q0.y) * f0.y + __int_as_float(q0.w) * f1.y
                + __int_as_float(q1.y) * f2.y + __int_as_float(q1.w) * f3.y;
            j += 4;
        }
    }
    for (; j < deg; ++j) {
        int2 p = __ldcs(&erow[j]);
        float v = __int_as_float(p.y);
        float2 f = __half22float2(
            __ldg(reinterpret_cast<const __half2*>(e2 + (size_t)p.x * DIM) + lane));
        ax += v * f.x;
        ay += v * f.y;
    }
    float2 b  = reinterpret_cast<const float2*>(base_row_ptr)[lane];
    float2 f1 = __half22float2(
        __ldg(reinterpret_cast<const __half2*>(e1 + (size_t)row * DIM) + lane));
    float2 f2 = __half22float2(
        __ldg(reinterpret_cast<const __half2*>(e2 + (size_t)row * DIM) + lane));
    return make_float2((b.x + f1.x + f2.x + ax) * 0.25f,
                       (b.y + f1.y + f2.y + ay) * 0.25f);
}

__global__ void gather3_kernel(const float*  __restrict__ ue,
                               const float*  __restrict__ ie,
                               const __half* __restrict__ e1,
                               const __half* __restrict__ e2,
                               const int*    __restrict__ cnt,
                               const int2*   __restrict__ edges,
                               const int*    __restrict__ users,
                               const int*    __restrict__ items,
                               float*        __restrict__ out)
{
    int w    = (blockIdx.x * blockDim.x + threadIdx.x) >> 5;
    int lane = threadIdx.x & 31;
    if (w >= BATCH) return;

    int u = users[w];
    int t = items[w] + N_USERS;

    float2 uemb = final_row(u, ue + (size_t)u * DIM, e1, e2, cnt, edges, lane);
    float2 iemb = final_row(t, ie + (size_t)(t - N_USERS) * DIM, e1, e2, cnt, edges, lane);

    reinterpret_cast<float2*>(out + (size_t)w * DIM)[lane] = uemb;
    reinterpret_cast<float2*>(out + (size_t)BATCH * DIM + (size_t)w * DIM)[lane] = iemb;

    float dot = uemb.x * iemb.x + uemb.y * iemb.y;
    #pragma unroll
    for (int off = 16; off > 0; off >>= 1)
        dot += __shfl_down_sync(0xFFFFFFFFu, dot, off);
    if (lane == 0)
        out[(size_t)2 * BATCH * DIM + w] = dot;
}

// ---------------------------------------------------------------------------
// Launch. Inputs per metadata order:
//  0 user_embed f32  1 item_embed f32  2 edge_src i32  3 edge_dst i32
//  4 edge_val f32    5 users i32       6 items i32
// ---------------------------------------------------------------------------
extern "C" void kernel_launch(void* const* d_in, const int* in_sizes, int n_in,
                              void* d_out, int out_size)
{
    const float* ue = (const float*)d_in[0];
    const float* ie = (const float*)d_in[1];
    const int*   es = (const int*)  d_in[2];
    const int*   ed = (const int*)  d_in[3];
    const float* ev = (const float*)d_in[4];
    const int*   us = (const int*)  d_in[5];
    const int*   it = (const int*)  d_in[6];
    float* out = (float*)d_out;

    __half *b16, *e1, *e2;
    int *cnt, *bins, *bincur, *order;
    int2 *edges;
    cudaGetSymbolAddress((void**)&b16,    g_B16);
    cudaGetSymbolAddress((void**)&e1,     g_E1);
    cudaGetSymbolAddress((void**)&e2,     g_E2);
    cudaGetSymbolAddress((void**)&cnt,    g_cnt);
    cudaGetSymbolAddress((void**)&edges,  g_edges);
    cudaGetSymbolAddress((void**)&bins,   g_bins);
    cudaGetSymbolAddress((void**)&bincur, g_bincur);
    cudaGetSymbolAddress((void**)&order,  g_order);

    const int e4_blocks   = (N_EDGES / 4 + 255) / 256;
    const int conv_blocks = (N_TOTAL * DIM / 4 + 255) / 256;
    const int spmm_blocks = (N_TOTAL * 8 + 255) / 256;
    const int sort_blocks = (N_TOTAL + 1023) / 1024;

    // --- base -> fp16 table (+ zero cnt/bins/bincur) ---
    convert_base_kernel<<<conv_blocks, 256>>>(ue, ie, b16, cnt, bins, bincur);

    // --- one-pass padded-CSR build ---
    pad_scatter_kernel<<<e4_blocks, 256>>>((const int4*)es, (const int4*)ed,
                                           (const float4*)ev, cnt, edges);

    // --- degree sort of rows (counting sort, 65 bins; scan fused into place) ---
    deghist_kernel<<<sort_blocks, 1024>>>(cnt, bins);
    place_kernel  <<<sort_blocks, 1024>>>(cnt, bins, bincur, order);

    // --- 2 fp16 SpMM layers over degree-sorted rows ---
    spmm_h_kernel<<<spmm_blocks, 256>>>(b16, e1, cnt, edges, order);
    spmm_h_kernel<<<spmm_blocks, 256>>>(e1,  e2, cnt, edges, order);

    // --- fused layer-3 + gather + dot ---
    gather3_kernel<<<(BATCH * 32 + 255) / 256, 256>>>(ue, ie, e1, e2, cnt, edges,
                                                      us, it, out);
}

// round 13
// speedup vs baseline: 1.0590x; 1.0477x over previous
#include <cuda_runtime.h>
#include <cuda_fp16.h>
#include <cstdint>

#define N_USERS 200000
#define N_ITEMS 100000
#define N_TOTAL 300000
#define DIM     64
#define N_EDGES 4800000
#define BATCH   16384
#define PAD     64          // padded slots per row; P(deg>64) ~ e^-45 for Poisson(16)

#define NWARPCH (N_TOTAL / 4)   // 75000 sorted 4-row chunks (one per warp)
#define WSTRIDE 593             // coprime with 75000 -> uniform wave sampling

// fused build: every 5th block scatters (4688 needed), the rest convert (18750 needed)
#define BUILD_BLOCKS 23440

// ---------------------------------------------------------------------------
// Device-global scratch (no allocation allowed).
// ---------------------------------------------------------------------------
__device__ __half g_B16[N_TOTAL * DIM];              // fp16 copy of base embeddings
__device__ __half g_E1 [N_TOTAL * DIM];              // layer-1 output (fp16)
__device__ __half g_E2 [N_TOTAL * DIM];              // layer-2 output (fp16)
__device__ int    g_cnt [N_TOTAL];                   // per-row degree counters
__device__ int2   g_edges[(size_t)N_TOTAL * PAD];    // padded CSR {src, val bits}
__device__ int    g_bins  [PAD + 1];                 // degree histogram
__device__ int    g_bincur[PAD + 1];                 // per-bin running cursors
__device__ int    g_order [N_TOTAL];                 // rows sorted by degree

__device__ __forceinline__ unsigned h2u(__half2 h)
{
    return *reinterpret_cast<unsigned*>(&h);
}

// ---------------------------------------------------------------------------
// Fused convert + padded-CSR scatter with INTERLEAVED role assignment:
// blockIdx % 5 == 0 -> scatter 4 edges/thread; else -> fp16 convert.
// Each scheduling wave carries a 1:4 mix, so the DRAM-stream (convert) and
// L2-atomic/random-store (scatter) paths overlap instead of serializing.
// cnt[] pre-zeroed via one cudaMemsetAsync; bins/bincur zeroed by block 1.
// ---------------------------------------------------------------------------
__global__ void build_kernel(const float*  __restrict__ ue,
                             const float*  __restrict__ ie,
                             __half*       __restrict__ b16,
                             const int4*   __restrict__ es4,
                             const int4*   __restrict__ ed4,
                             const float4* __restrict__ ev4,
                             int* __restrict__ cnt,
                             int2* __restrict__ edges,
                             int* __restrict__ bins,
                             int* __restrict__ bincur)
{
    int b = blockIdx.x;
    if (b % 5 == 0) {
        // --- scatter role: 4 edges per thread ---
        int i = (b / 5) * blockDim.x + threadIdx.x;
        if (i >= N_EDGES / 4) return;
        int4   s = __ldcs(&es4[i]);
        int4   d = __ldcs(&ed4[i]);
        float4 v = __ldcs(&ev4[i]);
        int p0 = atomicAdd(&cnt[d.x], 1);
        int p1 = atomicAdd(&cnt[d.y], 1);
        int p2 = atomicAdd(&cnt[d.z], 1);
        int p3 = atomicAdd(&cnt[d.w], 1);
        if (p0 < PAD) edges[(size_t)d.x * PAD + p0] = make_int2(s.x, __float_as_int(v.x));
        if (p1 < PAD) edges[(size_t)d.y * PAD + p1] = make_int2(s.y, __float_as_int(v.y));
        if (p2 < PAD) edges[(size_t)d.z * PAD + p2] = make_int2(s.z, __float_as_int(v.z));
        if (p3 < PAD) edges[(size_t)d.w * PAD + p3] = make_int2(s.w, __float_as_int(v.w));
    } else {
        // --- convert role ---
        if (b == 1 && threadIdx.x <= PAD) {       // bins/bincur consumed only later
            bins[threadIdx.x]   = 0;
            bincur[threadIdx.x] = 0;
        }
        const int total4 = N_TOTAL * DIM / 4;
        const int user4  = N_USERS * DIM / 4;
        int cb = (b / 5) * 4 + (b % 5 - 1);
        int i  = cb * blockDim.x + threadIdx.x;
        if (i >= total4) return;
        float4 v = (i < user4) ? __ldg(reinterpret_cast<const float4*>(ue) + i)
                               : __ldg(reinterpret_cast<const float4*>(ie) + (i - user4));
        uint2 o;
        o.x = h2u(__float22half2_rn(make_float2(v.x, v.y)));
        o.y = h2u(__float22half2_rn(make_float2(v.z, v.w)));
        reinterpret_cast<uint2*>(b16)[i] = o;
    }
}

// ---------------------------------------------------------------------------
// degree histogram (shared-memory aggregated)
// ---------------------------------------------------------------------------
__global__ void deghist_kernel(const int* __restrict__ cnt, int* bins)
{
    __shared__ int h[PAD + 1];
    if (threadIdx.x <= PAD) h[threadIdx.x] = 0;
    __syncthreads();
    int i = blockIdx.x * blockDim.x + threadIdx.x;
    if (i < N_TOTAL) {
        int d = cnt[i]; d = (d > PAD) ? PAD : d;
        atomicAdd(&h[d], 1);
    }
    __syncthreads();
    if (threadIdx.x <= PAD && h[threadIdx.x] > 0)
        atomicAdd(&bins[threadIdx.x], h[threadIdx.x]);
}

// place rows into degree-sorted order; each block computes the 65-bin
// exclusive scan locally (global bins[] is final).
__global__ void place_kernel(const int* __restrict__ cnt,
                             const int* __restrict__ bins,
                             int* bincur, int* order)
{
    __shared__ int h[PAD + 1];
    __shared__ int base[PAD + 1];
    __shared__ int scan[PAD + 1];
    int tid = threadIdx.x;
    if (tid <= PAD) h[tid] = 0;
    if (tid == 0) {
        int run = 0;
        #pragma unroll
        for (int b = 0; b <= PAD; ++b) { scan[b] = run; run += __ldg(&bins[b]); }
    }
    __syncthreads();
    int i = blockIdx.x * blockDim.x + tid;
    int deg = 0, lpos = 0;
    if (i < N_TOTAL) {
        deg = cnt[i]; deg = (deg > PAD) ? PAD : deg;
        lpos = atomicAdd(&h[deg], 1);
    }
    __syncthreads();
    if (tid <= PAD)
        base[tid] = scan[tid] + ((h[tid] > 0) ? atomicAdd(&bincur[tid], h[tid]) : 0);
    __syncthreads();
    if (i < N_TOTAL) order[base[deg] + lpos] = i;
}

// ---------------------------------------------------------------------------
// fp16 row-wise SpMM over degree-sorted rows, coprime warp->chunk remap,
// software-pipelined edge loads (__ldcs, evict-first). 8 lanes per dst row;
// each lane owns one 16-byte chunk. fp32 accumulation, fp16 output.
// ---------------------------------------------------------------------------
__device__ __forceinline__ void fma8(float acc[8], float v, uint4 raw)
{
    float2 f0 = __half22float2(*reinterpret_cast<__half2*>(&raw.x));
    float2 f1 = __half22float2(*reinterpret_cast<__half2*>(&raw.y));
    float2 f2 = __half22float2(*reinterpret_cast<__half2*>(&raw.z));
    float2 f3 = __half22float2(*reinterpret_cast<__half2*>(&raw.w));
    acc[0] += v * f0.x; acc[1] += v * f0.y;
    acc[2] += v * f1.x; acc[3] += v * f1.y;
    acc[4] += v * f2.x; acc[5] += v * f2.y;
    acc[6] += v * f3.x; acc[7] += v * f3.y;
}

__global__ void spmm_h_kernel(const __half* __restrict__ src,
                              __half*       __restrict__ dst,
                              const int*    __restrict__ cnt,
                              const int2*   __restrict__ edges,
                              const int*    __restrict__ order)
{
    int gid   = blockIdx.x * blockDim.x + threadIdx.x;
    int warp  = gid >> 5;                      // global warp id, [0, NWARPCH)
    if (warp >= NWARPCH) return;
    int sub   = (threadIdx.x >> 3) & 3;        // 4 subwarps of 8 lanes
    int lane  = threadIdx.x & 7;

    // coprime remap: warp -> sorted 4-row chunk (uniform degree per wave)
    long long c = ((long long)warp * WSTRIDE) % NWARPCH;
    int ridx = (int)c * 4 + sub;
    int row  = __ldg(&order[ridx]);

    int deg = __ldg(&cnt[row]);
    deg = (deg > PAD) ? PAD : deg;
    const int2* erow = edges + (size_t)row * PAD;

    float acc[8] = {0.f, 0.f, 0.f, 0.f, 0.f, 0.f, 0.f, 0.f};

    int j = 0;
    if (deg >= 4) {
        int4 q0 = __ldcs(reinterpret_cast<const int4*>(erow));
        int4 q1 = __ldcs(reinterpret_cast<const int4*>(erow + 2));
        for (; j + 7 < deg; j += 4) {
            int4 n0 = __ldcs(reinterpret_cast<const int4*>(erow + j + 4));
            int4 n1 = __ldcs(reinterpret_cast<const int4*>(erow + j + 6));
            uint4 r0 = __ldg(reinterpret_cast<const uint4*>(src + (size_t)q0.x * DIM) + lane);
            uint4 r1 = __ldg(reinterpret_cast<const uint4*>(src + (size_t)q0.z * DIM) + lane);
            uint4 r2 = __ldg(reinterpret_cast<const uint4*>(src + (size_t)q1.x * DIM) + lane);
            uint4 r3 = __ldg(reinterpret_cast<const uint4*>(src + (size_t)q1.z * DIM) + lane);
            fma8(acc, __int_as_float(q0.y), r0);
            fma8(acc, __int_as_float(q0.w), r1);
            fma8(acc, __int_as_float(q1.y), r2);
            fma8(acc, __int_as_float(q1.w), r3);
            q0 = n0; q1 = n1;
        }
        // drain the held quad (edges j..j+3, guaranteed valid)
        {
            uint4 r0 = __ldg(reinterpret_cast<const uint4*>(src + (size_t)q0.x * DIM) + lane);
            uint4 r1 = __ldg(reinterpret_cast<const uint4*>(src + (size_t)q0.z * DIM) + lane);
            uint4 r2 = __ldg(reinterpret_cast<const uint4*>(src + (size_t)q1.x * DIM) + lane);
            uint4 r3 = __ldg(reinterpret_cast<const uint4*>(src + (size_t)q1.z * DIM) + lane);
            fma8(acc, __int_as_float(q0.y), r0);
            fma8(acc, __int_as_float(q0.w), r1);
            fma8(acc, __int_as_float(q1.y), r2);
            fma8(acc, __int_as_float(q1.w), r3);
            j += 4;
        }
    }
    if (j + 1 < deg) {
        int4 q0 = __ldcs(reinterpret_cast<const int4*>(erow + j));
        uint4 r0 = __ldg(reinterpret_cast<const uint4*>(src + (size_t)q0.x * DIM) + lane);
        uint4 r1 = __ldg(reinterpret_cast<const uint4*>(src + (size_t)q0.z * DIM) + lane);
        fma8(acc, __int_as_float(q0.y), r0);
        fma8(acc, __int_as_float(q0.w), r1);
        j += 2;
    }
    if (j < deg) {
        int2 p0 = __ldcs(&erow[j]);
        uint4 r0 = __ldg(reinterpret_cast<const uint4*>(src + (size_t)p0.x * DIM) + lane);
        fma8(acc, __int_as_float(p0.y), r0);
    }

    uint4 o;
    o.x = h2u(__float22half2_rn(make_float2(acc[0], acc[1])));
    o.y = h2u(__float22half2_rn(make_float2(acc[2], acc[3])));
    o.z = h2u(__float22half2_rn(make_float2(acc[4], acc[5])));
    o.w = h2u(__float22half2_rn(make_float2(acc[6], acc[7])));
    reinterpret_cast<uint4*>(dst + (size_t)row * DIM)[lane] = o;
}

// ---------------------------------------------------------------------------
// Fused layer-3 + final gather. One warp per batch entry; each lane owns a
// half2 column pair. Pipelined edge loop, __ldcs edge reads.
// Output layout: [users_emb B*64][items_emb B*64][scores B]
// ---------------------------------------------------------------------------
__device__ __forceinline__ float2 final_row(int row,
                                            const float*  __restrict__ base_row_ptr,
                                            const __half* __restrict__ e1,
                                            const __half* __restrict__ e2,
                                            const int*    __restrict__ cnt,
                                            const int2*   __restrict__ edges,
                                            int lane)
{
    float ax = 0.f, ay = 0.f;
    int deg = __ldg(&cnt[row]);
    deg = (deg > PAD) ? PAD : deg;
    const int2* erow = edges + (size_t)row * PAD;

    int j = 0;
    if (deg >= 4) {
        int4 q0 = __ldcs(reinterpret_cast<const int4*>(erow));
        int4 q1 = __ldcs(reinterpret_cast<const int4*>(erow + 2));
        for (; j + 7 < deg; j += 4) {
            int4 n0 = __ldcs(reinterpret_cast<const int4*>(erow + j + 4));
            int4 n1 = __ldcs(reinterpret_cast<const int4*>(erow + j + 6));
            float2 f0 = __half22float2(
                __ldg(reinterpret_cast<const __half2*>(e2 + (size_t)q0.x * DIM) + lane));
            float2 f1 = __half22float2(
                __ldg(reinterpret_cast<const __half2*>(e2 + (size_t)q0.z * DIM) + lane));
            float2 f2 = __half22float2(
                __ldg(reinterpret_cast<const __half2*>(e2 + (size_t)q1.x * DIM) + lane));
            float2 f3 = __half22float2(
                __ldg(reinterpret_cast<const __half2*>(e2 + (size_t)q1.z * DIM) + lane));
            ax += __int_as_float(q0.y) * f0.x + __int_as_float(q0.w) * f1.x
                + __int_as_float(q1.y) * f2.x + __int_as_float(q1.w) * f3.x;
            ay += __int_as_float(q0.y) * f0.y + __int_as_float(q0.w) * f1.y
                + __int_as_float(q1.y) * f2.y + __int_as_float(q1.w) * f3.y;
            q0 = n0; q1 = n1;
        }
        {
            float2 f0 = __half22float2(
                __ldg(reinterpret_cast<const __half2*>(e2 + (size_t)q0.x * DIM) + lane));
            float2 f1 = __half22float2(
                __ldg(reinterpret_cast<const __half2*>(e2 + (size_t)q0.z * DIM) + lane));
            float2 f2 = __half22float2(
                __ldg(reinterpret_cast<const __half2*>(e2 + (size_t)q1.x * DIM) + lane));
            float2 f3 = __half22float2(
                __ldg(reinterpret_cast<const __half2*>(e2 + (size_t)q1.z * DIM) + lane));
            ax += __int_as_float(q0.y) * f0.x + __int_as_float(q0.w) * f1.x
                + __int_as_float(q1.y) * f2.x + __int_as_float(q1.w) * f3.x;
            ay += __int_as_float(q0.y) * f0.y + __int_as_float(q0.w) * f1.y
                + __int_as_float(q1.y) * f2.y + __int_as_float(q1.w) * f3.y;
            j += 4;
        }
    }
    for (; j < deg; ++j) {
        int2 p = __ldcs(&erow[j]);
        float v = __int_as_float(p.y);
        float2 f = __half22float2(
            __ldg(reinterpret_cast<const __half2*>(e2 + (size_t)p.x * DIM) + lane));
        ax += v * f.x;
        ay += v * f.y;
    }
    float2 b  = reinterpret_cast<const float2*>(base_row_ptr)[lane];
    float2 f1 = __half22float2(
        __ldg(reinterpret_cast<const __half2*>(e1 + (size_t)row * DIM) + lane));
    float2 f2 = __half22float2(
        __ldg(reinterpret_cast<const __half2*>(e2 + (size_t)row * DIM) + lane));
    return make_float2((b.x + f1.x + f2.x + ax) * 0.25f,
                       (b.y + f1.y + f2.y + ay) * 0.25f);
}

__global__ void gather3_kernel(const float*  __restrict__ ue,
                               const float*  __restrict__ ie,
                               const __half* __restrict__ e1,
                               const __half* __restrict__ e2,
                               const int*    __restrict__ cnt,
                               const int2*   __restrict__ edges,
                               const int*    __restrict__ users,
                               const int*    __restrict__ items,
                               float*        __restrict__ out)
{
    int w    = (blockIdx.x * blockDim.x + threadIdx.x) >> 5;
    int lane = threadIdx.x & 31;
    if (w >= BATCH) return;

    int u = users[w];
    int t = items[w] + N_USERS;

    float2 uemb = final_row(u, ue + (size_t)u * DIM, e1, e2, cnt, edges, lane);
    float2 iemb = final_row(t, ie + (size_t)(t - N_USERS) * DIM, e1, e2, cnt, edges, lane);

    reinterpret_cast<float2*>(out + (size_t)w * DIM)[lane] = uemb;
    reinterpret_cast<float2*>(out + (size_t)BATCH * DIM + (size_t)w * DIM)[lane] = iemb;

    float dot = uemb.x * iemb.x + uemb.y * iemb.y;
    #pragma unroll
    for (int off = 16; off > 0; off >>= 1)
        dot += __shfl_down_sync(0xFFFFFFFFu, dot, off);
    if (lane == 0)
        out[(size_t)2 * BATCH * DIM + w] = dot;
}

// ---------------------------------------------------------------------------
// Launch. Inputs per metadata order:
//  0 user_embed f32  1 item_embed f32  2 edge_src i32  3 edge_dst i32
//  4 edge_val f32    5 users i32       6 items i32
// ---------------------------------------------------------------------------
extern "C" void kernel_launch(void* const* d_in, const int* in_sizes, int n_in,
                              void* d_out, int out_size)
{
    const float* ue = (const float*)d_in[0];
    const float* ie = (const float*)d_in[1];
    const int*   es = (const int*)  d_in[2];
    const int*   ed = (const int*)  d_in[3];
    const float* ev = (const float*)d_in[4];
    const int*   us = (const int*)  d_in[5];
    const int*   it = (const int*)  d_in[6];
    float* out = (float*)d_out;

    __half *b16, *e1, *e2;
    int *cnt, *bins, *bincur, *order;
    int2 *edges;
    cudaGetSymbolAddress((void**)&b16,    g_B16);
    cudaGetSymbolAddress((void**)&e1,     g_E1);
    cudaGetSymbolAddress((void**)&e2,     g_E2);
    cudaGetSymbolAddress((void**)&cnt,    g_cnt);
    cudaGetSymbolAddress((void**)&edges,  g_edges);
    cudaGetSymbolAddress((void**)&bins,   g_bins);
    cudaGetSymbolAddress((void**)&bincur, g_bincur);
    cudaGetSymbolAddress((void**)&order,  g_order);

    const int spmm_blocks = (N_TOTAL * 8 + 255) / 256;
    const int sort_blocks = (N_TOTAL + 1023) / 1024;

    // zero degree counters (graph-capturable, not an allocation)
    cudaMemsetAsync(cnt, 0, N_TOTAL * sizeof(int));

    // --- fused convert + padded-CSR scatter (interleaved roles) ---
    build_kernel<<<BUILD_BLOCKS, 256>>>(ue, ie, b16,
                                        (const int4*)es, (const int4*)ed,
                                        (const float4*)ev,
                                        cnt, edges, bins, bincur);

    // --- degree sort of rows (counting sort, 65 bins; scan fused into place) ---
    deghist_kernel<<<sort_blocks, 1024>>>(cnt, bins);
    place_kernel  <<<sort_blocks, 1024>>>(cnt, bins, bincur, order);

    // --- 2 fp16 SpMM layers over degree-sorted rows ---
    spmm_h_kernel<<<spmm_blocks, 256>>>(b16, e1, cnt, edges, order);
    spmm_h_kernel<<<spmm_blocks, 256>>>(e1,  e2, cnt, edges, order);

    // --- fused layer-3 + gather + dot ---
    gather3_kernel<<<(BATCH * 32 + 255) / 256, 256>>>(ue, ie, e1, e2, cnt, edges,
                                                      us, it, out);
}